// round 14
// baseline (speedup 1.0000x reference)
#include <cuda_runtime.h>
#include <cuda_fp16.h>
#include <cstdint>

#define NN   32
#define WH   4096
#define CC   256
#define SCALE 0.0625f      // 1/sqrt(256)
#define BSCALE 64.0f       // pre-scale on B to keep folded ca*W in fp16 normal range
#define INV_BSCALE 0.015625f
#define GB   8             // batches per group
#define NG   4             // groups

// Scratch (device globals — no allocations allowed)
__device__ float g_q[NN * CC];
__device__ float g_partS[NN * 16 * CC];
__device__ float g_palog[NN * WH];
__device__ float g_ca[NN * CC];
__device__ float g_pa[NN * WH];
__device__ __align__(16) unsigned short g_Ah[(size_t)NN * WH * CC]; // fp16(inputs)
__device__ __align__(16) unsigned short g_Wh[CC * CC];              // fp16(W^T) [co][ci]
__device__ __align__(16) unsigned short g_Bh[NN * CC * CC];         // per-batch 64*ca*W

// ---------------------------------------------------------------------------
// Helpers (baseline PTX — plain sm_103 target)
// ---------------------------------------------------------------------------
__device__ __forceinline__ void ldm4(uint32_t* r, uint32_t addr) {
    asm volatile("ldmatrix.sync.aligned.m8n8.x4.shared.b16 {%0,%1,%2,%3}, [%4];"
                 : "=r"(r[0]), "=r"(r[1]), "=r"(r[2]), "=r"(r[3]) : "r"(addr));
}
__device__ __forceinline__ void mma_f16(float* c, const uint32_t* a,
                                        uint32_t b0, uint32_t b1) {
    asm volatile(
        "mma.sync.aligned.m16n8k16.row.col.f32.f16.f16.f32 "
        "{%0,%1,%2,%3}, {%4,%5,%6,%7}, {%8,%9}, {%0,%1,%2,%3};"
        : "+f"(c[0]), "+f"(c[1]), "+f"(c[2]), "+f"(c[3])
        : "r"(a[0]), "r"(a[1]), "r"(a[2]), "r"(a[3]), "r"(b0), "r"(b1));
}
__device__ __forceinline__ uint32_t pack_h2(float a, float b) {
    __half2 t = __floats2half2_rn(a, b);
    return *reinterpret_cast<uint32_t*>(&t);
}
__device__ __forceinline__ void cp16(uint32_t dst, const void* src) {
    asm volatile("cp.async.cg.shared.global [%0], [%1], 16;"
                 :: "r"(dst), "l"(src) : "memory");
}

// ---------------------------------------------------------------------------
// K1: q[n,c] = leaky_relu_0.3( style @ w_dense )
// ---------------------------------------------------------------------------
__global__ void k_q(const float* __restrict__ style, const float* __restrict__ wd) {
    int n = blockIdx.x, c = threadIdx.x;
    __shared__ float s[CC];
    s[c] = style[n * CC + c];
    __syncthreads();
    float acc = 0.f;
#pragma unroll 8
    for (int k = 0; k < CC; k++) acc = fmaf(s[k], wd[k * CC + c], acc);
    g_q[n * CC + c] = acc > 0.f ? acc : 0.3f * acc;
}

// ---------------------------------------------------------------------------
// K_wh: tiled transpose wc[ci][co] fp32 -> g_Wh[co][ci] fp16. grid(8,8), 256 thr.
// ---------------------------------------------------------------------------
__global__ void k_wh(const float* __restrict__ wc) {
    __shared__ float tile[32][33];
    int tx = threadIdx.x & 31, ty = threadIdx.x >> 5;
    int ci0 = blockIdx.y * 32, co0 = blockIdx.x * 32;
#pragma unroll
    for (int j = 0; j < 4; j++)
        tile[ty + j * 8][tx] = wc[(size_t)(ci0 + ty + j * 8) * CC + co0 + tx];
    __syncthreads();
#pragma unroll
    for (int j = 0; j < 4; j++) {
        int co = co0 + ty + j * 8;
        g_Wh[(size_t)co * CC + ci0 + tx] =
            __half_as_ushort(__float2half_rn(tile[tx][ty + j * 8]));
    }
}

// ---------------------------------------------------------------------------
// K2: one pass over a group of batches: pa_logits + column sums + fp16 A copy
// grid=(16 chunks, GB), block=256
// ---------------------------------------------------------------------------
__global__ void k_pa_colsum(const float* __restrict__ in, int nb0) {
    int n = nb0 + blockIdx.y, chunk = blockIdx.x;
    int tid = threadIdx.x, lane = tid & 31, w = tid >> 5;

    const float4* q4 = reinterpret_cast<const float4*>(g_q + (size_t)n * CC);
    float4 qa = q4[lane * 2], qb = q4[lane * 2 + 1];

    float4 cs0 = {0.f, 0.f, 0.f, 0.f}, cs1 = {0.f, 0.f, 0.f, 0.f};
    int pbase = chunk * 256 + w * 32;
    const float4* base4 =
        reinterpret_cast<const float4*>(in + ((size_t)n * WH + pbase) * CC);

    for (int i = 0; i < 32; i++) {
        const float4* r = base4 + (size_t)i * (CC / 4);
        float4 v0 = r[lane * 2], v1 = r[lane * 2 + 1];
        float d = v0.x * qa.x + v0.y * qa.y + v0.z * qa.z + v0.w * qa.w
                + v1.x * qb.x + v1.y * qb.y + v1.z * qb.z + v1.w * qb.w;
        cs0.x += v0.x; cs0.y += v0.y; cs0.z += v0.z; cs0.w += v0.w;
        cs1.x += v1.x; cs1.y += v1.y; cs1.z += v1.z; cs1.w += v1.w;
        uint4 hc;
        hc.x = pack_h2(v0.x, v0.y); hc.y = pack_h2(v0.z, v0.w);
        hc.z = pack_h2(v1.x, v1.y); hc.w = pack_h2(v1.z, v1.w);
        *reinterpret_cast<uint4*>(
            g_Ah + ((size_t)n * WH + pbase + i) * CC + lane * 8) = hc;
#pragma unroll
        for (int o = 16; o; o >>= 1) d += __shfl_xor_sync(0xffffffffu, d, o);
        if (lane == 0) g_palog[(size_t)n * WH + pbase + i] = d * SCALE;
    }

    __shared__ float sm[8 * CC];
    float* smw = sm + w * CC + lane * 8;
    smw[0] = cs0.x; smw[1] = cs0.y; smw[2] = cs0.z; smw[3] = cs0.w;
    smw[4] = cs1.x; smw[5] = cs1.y; smw[6] = cs1.z; smw[7] = cs1.w;
    __syncthreads();
    float ssum = 0.f;
#pragma unroll
    for (int ww = 0; ww < 8; ww++) ssum += sm[ww * CC + tid];
    g_partS[((size_t)n * 16 + chunk) * CC + tid] = ssum;
}

// ---------------------------------------------------------------------------
// K3 (fused): blocks 0..GB-1 -> channel softmax; GB..2GB-1 -> position softmax
// ---------------------------------------------------------------------------
__global__ void k_soft(int nb0) {
    int b = blockIdx.x, tid = threadIdx.x;
    __shared__ float red[256];
    if (b < GB) {
        int n = nb0 + b;
        float S = 0.f;
#pragma unroll
        for (int k = 0; k < 16; k++) S += g_partS[((size_t)n * 16 + k) * CC + tid];
        float logit = S * g_q[n * CC + tid] * SCALE;
        red[tid] = logit; __syncthreads();
        for (int s = 128; s; s >>= 1) {
            if (tid < s) red[tid] = fmaxf(red[tid], red[tid + s]);
            __syncthreads();
        }
        float m = red[0]; __syncthreads();
        float e = expf(logit - m);
        red[tid] = e; __syncthreads();
        for (int s = 128; s; s >>= 1) {
            if (tid < s) red[tid] += red[tid + s];
            __syncthreads();
        }
        g_ca[n * CC + tid] = e / red[0];
    } else {
        int n = nb0 + b - GB;
        float v[16];
        float m = -1e30f;
#pragma unroll
        for (int i = 0; i < 16; i++) {
            v[i] = g_palog[(size_t)n * WH + i * 256 + tid];
            m = fmaxf(m, v[i]);
        }
        red[tid] = m; __syncthreads();
        for (int s = 128; s; s >>= 1) {
            if (tid < s) red[tid] = fmaxf(red[tid], red[tid + s]);
            __syncthreads();
        }
        m = red[0]; __syncthreads();
        float sum = 0.f;
#pragma unroll
        for (int i = 0; i < 16; i++) { v[i] = expf(v[i] - m); sum += v[i]; }
        red[tid] = sum; __syncthreads();
        for (int s = 128; s; s >>= 1) {
            if (tid < s) red[tid] += red[tid + s];
            __syncthreads();
        }
        float r = 1.f / red[0];
#pragma unroll
        for (int i = 0; i < 16; i++)
            g_pa[(size_t)n * WH + i * 256 + tid] = v[i] * r;
    }
}

// ---------------------------------------------------------------------------
// K_prepB: B_eff[n][co][ci] = fp16( 64 * ca[n][ci] * Wh[co][ci] ), coalesced.
// grid=(32 co-blocks of 8, GB), block=256.
// ---------------------------------------------------------------------------
__global__ void k_prepB(int nb0) {
    int n = nb0 + blockIdx.y;
    int co = blockIdx.x * 8 + (threadIdx.x >> 5);
    int ci0 = (threadIdx.x & 31) * 8;
    uint4 w = *reinterpret_cast<const uint4*>(g_Wh + (size_t)co * CC + ci0);
    const float4* cap = reinterpret_cast<const float4*>(g_ca + n * CC + ci0);
    float4 c0 = cap[0], c1 = cap[1];
    const __half2* wh = reinterpret_cast<const __half2*>(&w);
    uint4 o;
    float2 f;
    f = __half22float2(wh[0]);
    o.x = pack_h2(BSCALE * c0.x * f.x, BSCALE * c0.y * f.y);
    f = __half22float2(wh[1]);
    o.y = pack_h2(BSCALE * c0.z * f.x, BSCALE * c0.w * f.y);
    f = __half22float2(wh[2]);
    o.z = pack_h2(BSCALE * c1.x * f.x, BSCALE * c1.y * f.y);
    f = __half22float2(wh[3]);
    o.w = pack_h2(BSCALE * c1.z * f.x, BSCALE * c1.w * f.y);
    *reinterpret_cast<uint4*>(g_Bh + ((size_t)n * CC + co) * CC + ci0) = o;
}

// ---------------------------------------------------------------------------
// K4: HMMA fp16 GEMM, CTA tile 128x128, warp tile 32x64, 2 CTAs/SM,
// 3-buffer one-sync-per-chunk pipeline (at legacy mma.sync tensor ceiling).
// grid=(32 mtiles, 2 ntiles, GB), block=256.
// ---------------------------------------------------------------------------
#define RS     144
#define A_OFF  0
#define B_OFF  18432
#define BUFB   36864
#define SMEMB  (3 * BUFB)            // 110592/CTA -> 221184/SM @2 CTAs

__global__ void __launch_bounds__(256, 2)
k_conv_mma(float* __restrict__ out, int nb0) {
    extern __shared__ char smem[];
    const uint32_t sb = (uint32_t)__cvta_generic_to_shared(smem);
    const int tid = threadIdx.x, lane = tid & 31, wid = tid >> 5;
    const int nb = nb0 + blockIdx.z;
    const int m0 = blockIdx.x * 128;
    const int n0 = blockIdx.y * 128;
    const int warp_m = (wid & 3) * 32, warp_n = (wid >> 2) * 64;
    const int q = lane >> 3;

    const uint32_t aBase = sb + A_OFF
        + (uint32_t)(warp_m + (lane & 7) + ((q & 1) << 3)) * RS + ((q >> 1) << 4);
    const uint32_t bBase = sb + B_OFF
        + (uint32_t)(warp_n + (lane & 7) + ((q >> 1) << 3)) * RS + ((q & 1) << 4);

    const unsigned short* Asrc = g_Ah + ((size_t)nb * WH + m0) * CC;
    const unsigned short* Bsrc = g_Bh + ((size_t)nb * CC + n0) * CC;

    float acc[2][8][4];
#pragma unroll
    for (int i = 0; i < 2; i++)
#pragma unroll
        for (int j = 0; j < 8; j++)
#pragma unroll
            for (int t = 0; t < 4; t++) acc[i][j][t] = 0.f;

    auto issue = [&](int c, int buf) {
        uint32_t d = sb + (uint32_t)buf * BUFB;
#pragma unroll
        for (int j = 0; j < 4; j++) {
            int o = tid + 256 * j, row = o >> 3, seg = o & 7;
            cp16(d + A_OFF + row * RS + seg * 16,
                 Asrc + (size_t)row * CC + c * 64 + seg * 8);
        }
#pragma unroll
        for (int j = 0; j < 4; j++) {
            int o = tid + 256 * j, row = o >> 3, seg = o & 7;
            cp16(d + B_OFF + row * RS + seg * 16,
                 Bsrc + (size_t)row * CC + c * 64 + seg * 8);
        }
        asm volatile("cp.async.commit_group;" ::: "memory");
    };

    issue(0, 0);
    issue(1, 1);
#pragma unroll
    for (int c = 0; c < 4; c++) {
        if (c < 3)
            asm volatile("cp.async.wait_group 1;" ::: "memory");
        else
            asm volatile("cp.async.wait_group 0;" ::: "memory");
        __syncthreads();
        if (c + 2 < 4) issue(c + 2, (c + 2) % 3);

        const uint32_t bo = (uint32_t)(c % 3) * BUFB;
#pragma unroll
        for (int ks = 0; ks < 4; ks++) {
            const uint32_t ko = bo + ks * 32;
            uint32_t ah[2][4];
            ldm4(ah[0], aBase + ko);
            ldm4(ah[1], aBase + ko + 16 * RS);
#pragma unroll
            for (int p = 0; p < 4; p++) {
                uint32_t bh[4];
                ldm4(bh, bBase + ko + p * 16 * RS);
                mma_f16(acc[0][2 * p],     ah[0], bh[0], bh[1]);
                mma_f16(acc[0][2 * p + 1], ah[0], bh[2], bh[3]);
                mma_f16(acc[1][2 * p],     ah[1], bh[0], bh[1]);
                mma_f16(acc[1][2 * p + 1], ah[1], bh[2], bh[3]);
            }
        }
    }

    const int g = lane >> 2, tg = lane & 3;
#pragma unroll
    for (int mt = 0; mt < 2; mt++) {
        int r0 = m0 + warp_m + mt * 16 + g;
        float pa0 = g_pa[(size_t)nb * WH + r0] * INV_BSCALE;
        float pa1 = g_pa[(size_t)nb * WH + r0 + 8] * INV_BSCALE;
        float* o0 = out + ((size_t)nb * WH + r0) * CC + n0 + warp_n + tg * 2;
        float* o1 = o0 + 8 * CC;
#pragma unroll
        for (int nt = 0; nt < 8; nt++) {
            float v0 = acc[mt][nt][0], v1 = acc[mt][nt][1];
            float v2 = acc[mt][nt][2], v3 = acc[mt][nt][3];
            v0 = (v0 > 0.f ? v0 : 0.1f * v0) * pa0;
            v1 = (v1 > 0.f ? v1 : 0.1f * v1) * pa0;
            v2 = (v2 > 0.f ? v2 : 0.1f * v2) * pa1;
            v3 = (v3 > 0.f ? v3 : 0.1f * v3) * pa1;
            *reinterpret_cast<float2*>(o0 + nt * 8) = make_float2(v0, v1);
            *reinterpret_cast<float2*>(o1 + nt * 8) = make_float2(v2, v3);
        }
    }
}

// ---------------------------------------------------------------------------
// Launch: 4 batch-groups pipelined across 2 streams (fork/join via events) so
// the DRAM-bound colsum of group g+1 overlaps the tensor-bound conv of group g.
// ---------------------------------------------------------------------------
extern "C" void kernel_launch(void* const* d_in, const int* in_sizes, int n_in,
                              void* d_out, int out_size) {
    const float* in    = (const float*)d_in[0];  // [32,64,64,256]
    const float* style = (const float*)d_in[1];  // [32,256]
    const float* wd    = (const float*)d_in[2];  // [256,256]
    const float* wc    = (const float*)d_in[3];  // [1,1,256,256] -> [ci][co]
    float* out = (float*)d_out;

    static cudaStream_t s2 = nullptr;
    static cudaEvent_t evFork = nullptr, evJoin = nullptr;
    if (!s2) {
        cudaFuncSetAttribute(k_conv_mma,
                             cudaFuncAttributeMaxDynamicSharedMemorySize, SMEMB);
        cudaStreamCreateWithFlags(&s2, cudaStreamNonBlocking);
        cudaEventCreateWithFlags(&evFork, cudaEventDisableTiming);
        cudaEventCreateWithFlags(&evJoin, cudaEventDisableTiming);
    }

    k_q<<<NN, CC>>>(style, wd);
    k_wh<<<dim3(8, 8), 256>>>(wc);

    cudaEventRecord(evFork, 0);
    cudaStreamWaitEvent(s2, evFork, 0);

    for (int gidx = 0; gidx < NG; gidx++) {
        cudaStream_t s = (gidx & 1) ? s2 : (cudaStream_t)0;
        int nb0 = gidx * GB;
        k_pa_colsum<<<dim3(16, GB), 256, 0, s>>>(in, nb0);
        k_soft<<<2 * GB, 256, 0, s>>>(nb0);
        k_prepB<<<dim3(32, GB), 256, 0, s>>>(nb0);
        k_conv_mma<<<dim3(32, 2, GB), 256, SMEMB, s>>>(out, nb0);
    }

    cudaEventRecord(evJoin, s2);
    cudaStreamWaitEvent((cudaStream_t)0, evJoin, 0);
}

// round 15
// speedup vs baseline: 1.0978x; 1.0978x over previous
#include <cuda_runtime.h>
#include <cuda_fp16.h>
#include <cstdint>

#define NN   32
#define WH   4096
#define CC   256
#define SCALE 0.0625f      // 1/sqrt(256)
#define BSCALE 64.0f       // pre-scale on B to keep folded ca*W in fp16 normal range
#define INV_BSCALE 0.015625f

// Scratch (device globals — no allocations allowed)
__device__ float g_q[NN * CC];
__device__ float g_partS[NN * 16 * CC];
__device__ float g_palog[NN * WH];
__device__ float g_pa[NN * WH];
__device__ __align__(16) unsigned short g_Ah[(size_t)NN * WH * CC]; // fp16(inputs)
__device__ __align__(16) unsigned short g_Wh[CC * CC];              // fp16(W^T) [co][ci]
__device__ __align__(16) unsigned short g_Bh[NN * CC * CC];         // per-batch 64*ca*W

// ---------------------------------------------------------------------------
// Helpers (baseline PTX — plain sm_103 target)
// ---------------------------------------------------------------------------
__device__ __forceinline__ void ldm4(uint32_t* r, uint32_t addr) {
    asm volatile("ldmatrix.sync.aligned.m8n8.x4.shared.b16 {%0,%1,%2,%3}, [%4];"
                 : "=r"(r[0]), "=r"(r[1]), "=r"(r[2]), "=r"(r[3]) : "r"(addr));
}
__device__ __forceinline__ void mma_f16(float* c, const uint32_t* a,
                                        uint32_t b0, uint32_t b1) {
    asm volatile(
        "mma.sync.aligned.m16n8k16.row.col.f32.f16.f16.f32 "
        "{%0,%1,%2,%3}, {%4,%5,%6,%7}, {%8,%9}, {%0,%1,%2,%3};"
        : "+f"(c[0]), "+f"(c[1]), "+f"(c[2]), "+f"(c[3])
        : "r"(a[0]), "r"(a[1]), "r"(a[2]), "r"(a[3]), "r"(b0), "r"(b1));
}
__device__ __forceinline__ uint32_t pack_h2(float a, float b) {
    __half2 t = __floats2half2_rn(a, b);
    return *reinterpret_cast<uint32_t*>(&t);
}
__device__ __forceinline__ void cp16(uint32_t dst, const void* src) {
    asm volatile("cp.async.cg.shared.global [%0], [%1], 16;"
                 :: "r"(dst), "l"(src) : "memory");
}

// ---------------------------------------------------------------------------
// K_prep (fused): blocks 0..31 -> q = leaky0.3(style@wd);
// blocks 32..95 -> tiled transpose wc[ci][co] fp32 -> g_Wh[co][ci] fp16.
// ---------------------------------------------------------------------------
__global__ void k_prep(const float* __restrict__ style,
                       const float* __restrict__ wd,
                       const float* __restrict__ wc) {
    int b = blockIdx.x;
    if (b < NN) {
        int n = b, c = threadIdx.x;
        __shared__ float s[CC];
        s[c] = style[n * CC + c];
        __syncthreads();
        float acc = 0.f;
#pragma unroll 8
        for (int k = 0; k < CC; k++) acc = fmaf(s[k], wd[k * CC + c], acc);
        g_q[n * CC + c] = acc > 0.f ? acc : 0.3f * acc;
    } else {
        __shared__ float tile[32][33];
        int bb = b - NN;
        int tx = threadIdx.x & 31, ty = threadIdx.x >> 5;
        int co0 = (bb & 7) * 32, ci0 = (bb >> 3) * 32;
#pragma unroll
        for (int j = 0; j < 4; j++)
            tile[ty + j * 8][tx] = wc[(size_t)(ci0 + ty + j * 8) * CC + co0 + tx];
        __syncthreads();
#pragma unroll
        for (int j = 0; j < 4; j++) {
            int co = co0 + ty + j * 8;
            g_Wh[(size_t)co * CC + ci0 + tx] =
                __half_as_ushort(__float2half_rn(tile[tx][ty + j * 8]));
        }
    }
}

// ---------------------------------------------------------------------------
// K2: one pass over inputs: pa_logits + partial column sums + fp16 copy of A
// grid=(16 chunks, 32 n), block=256
// ---------------------------------------------------------------------------
__global__ void k_pa_colsum(const float* __restrict__ in) {
    int n = blockIdx.y, chunk = blockIdx.x;
    int tid = threadIdx.x, lane = tid & 31, w = tid >> 5;

    const float4* q4 = reinterpret_cast<const float4*>(g_q + (size_t)n * CC);
    float4 qa = q4[lane * 2], qb = q4[lane * 2 + 1];

    float4 cs0 = {0.f, 0.f, 0.f, 0.f}, cs1 = {0.f, 0.f, 0.f, 0.f};
    int pbase = chunk * 256 + w * 32;
    const float4* base4 =
        reinterpret_cast<const float4*>(in + ((size_t)n * WH + pbase) * CC);

    for (int i = 0; i < 32; i++) {
        const float4* r = base4 + (size_t)i * (CC / 4);
        float4 v0 = r[lane * 2], v1 = r[lane * 2 + 1];
        float d = v0.x * qa.x + v0.y * qa.y + v0.z * qa.z + v0.w * qa.w
                + v1.x * qb.x + v1.y * qb.y + v1.z * qb.z + v1.w * qb.w;
        cs0.x += v0.x; cs0.y += v0.y; cs0.z += v0.z; cs0.w += v0.w;
        cs1.x += v1.x; cs1.y += v1.y; cs1.z += v1.z; cs1.w += v1.w;
        uint4 hc;
        hc.x = pack_h2(v0.x, v0.y); hc.y = pack_h2(v0.z, v0.w);
        hc.z = pack_h2(v1.x, v1.y); hc.w = pack_h2(v1.z, v1.w);
        *reinterpret_cast<uint4*>(
            g_Ah + ((size_t)n * WH + pbase + i) * CC + lane * 8) = hc;
#pragma unroll
        for (int o = 16; o; o >>= 1) d += __shfl_xor_sync(0xffffffffu, d, o);
        if (lane == 0) g_palog[(size_t)n * WH + pbase + i] = d * SCALE;
    }

    __shared__ float sm[8 * CC];
    float* smw = sm + w * CC + lane * 8;
    smw[0] = cs0.x; smw[1] = cs0.y; smw[2] = cs0.z; smw[3] = cs0.w;
    smw[4] = cs1.x; smw[5] = cs1.y; smw[6] = cs1.z; smw[7] = cs1.w;
    __syncthreads();
    float ssum = 0.f;
#pragma unroll
    for (int ww = 0; ww < 8; ww++) ssum += sm[ww * CC + tid];
    g_partS[((size_t)n * 16 + chunk) * CC + tid] = ssum;
}

// ---------------------------------------------------------------------------
// K3 (fused): blocks 0..31 -> channel softmax + folded-B production for that
// batch (B_eff[n][co][ci] = fp16(64*ca[ci]*Wh[co][ci]), same fp32 ca bits as
// the standalone prepB). Blocks 32..63 -> position softmax.
// ---------------------------------------------------------------------------
__global__ void k_soft() {
    int b = blockIdx.x, tid = threadIdx.x;
    __shared__ float red[256];
    if (b < NN) {
        int n = b;
        float S = 0.f;
#pragma unroll
        for (int k = 0; k < 16; k++) S += g_partS[((size_t)n * 16 + k) * CC + tid];
        float logit = S * g_q[n * CC + tid] * SCALE;
        red[tid] = logit; __syncthreads();
        for (int s = 128; s; s >>= 1) {
            if (tid < s) red[tid] = fmaxf(red[tid], red[tid + s]);
            __syncthreads();
        }
        float m = red[0]; __syncthreads();
        float e = expf(logit - m);
        red[tid] = e; __syncthreads();
        for (int s = 128; s; s >>= 1) {
            if (tid < s) red[tid] += red[tid + s];
            __syncthreads();
        }
        __shared__ float cas[CC];
        cas[tid] = e / red[0];            // ca[n][tid], fp32 (same bits as before)
        __syncthreads();

        // Fused prepB: 256co x 32 ci-segments, coalesced read/modify/write.
        const int cor = tid >> 5;          // co row within group of 8
        const int ci0 = (tid & 31) * 8;    // ci segment
        const float* cap = cas + ci0;
        float c0 = cap[0], c1 = cap[1], c2 = cap[2], c3 = cap[3];
        float c4 = cap[4], c5 = cap[5], c6 = cap[6], c7 = cap[7];
#pragma unroll
        for (int j = 0; j < 32; j++) {
            int co = j * 8 + cor;
            uint4 w = *reinterpret_cast<const uint4*>(g_Wh + (size_t)co * CC + ci0);
            const __half2* wh = reinterpret_cast<const __half2*>(&w);
            uint4 o;
            float2 f;
            f = __half22float2(wh[0]);
            o.x = pack_h2(BSCALE * c0 * f.x, BSCALE * c1 * f.y);
            f = __half22float2(wh[1]);
            o.y = pack_h2(BSCALE * c2 * f.x, BSCALE * c3 * f.y);
            f = __half22float2(wh[2]);
            o.z = pack_h2(BSCALE * c4 * f.x, BSCALE * c5 * f.y);
            f = __half22float2(wh[3]);
            o.w = pack_h2(BSCALE * c6 * f.x, BSCALE * c7 * f.y);
            *reinterpret_cast<uint4*>(g_Bh + ((size_t)n * CC + co) * CC + ci0) = o;
        }
    } else {
        int n = b - NN;
        float v[16];
        float m = -1e30f;
#pragma unroll
        for (int i = 0; i < 16; i++) {
            v[i] = g_palog[(size_t)n * WH + i * 256 + tid];
            m = fmaxf(m, v[i]);
        }
        red[tid] = m; __syncthreads();
        for (int s = 128; s; s >>= 1) {
            if (tid < s) red[tid] = fmaxf(red[tid], red[tid + s]);
            __syncthreads();
        }
        m = red[0]; __syncthreads();
        float sum = 0.f;
#pragma unroll
        for (int i = 0; i < 16; i++) { v[i] = expf(v[i] - m); sum += v[i]; }
        red[tid] = sum; __syncthreads();
        for (int s = 128; s; s >>= 1) {
            if (tid < s) red[tid] += red[tid + s];
            __syncthreads();
        }
        float r = 1.f / red[0];
#pragma unroll
        for (int i = 0; i < 16; i++)
            g_pa[(size_t)n * WH + i * 256 + tid] = v[i] * r;
    }
}

// ---------------------------------------------------------------------------
// K4: HMMA fp16 GEMM, CTA tile 128x128, warp tile 32x64, 2 CTAs/SM,
// 3-buffer one-sync-per-chunk pipeline. Epilogue: leaky0.1 * pa/64.
// grid=(32 mtiles, 2 ntiles, 32 batch), block=256.
// ---------------------------------------------------------------------------
#define RS     144
#define A_OFF  0
#define B_OFF  18432
#define BUFB   36864
#define SMEMB  (3 * BUFB)            // 110592/CTA -> 221184/SM @2 CTAs

__global__ void __launch_bounds__(256, 2)
k_conv_mma(float* __restrict__ out) {
    extern __shared__ char smem[];
    const uint32_t sb = (uint32_t)__cvta_generic_to_shared(smem);
    const int tid = threadIdx.x, lane = tid & 31, wid = tid >> 5;
    const int nb = blockIdx.z;
    const int m0 = blockIdx.x * 128;
    const int n0 = blockIdx.y * 128;
    const int warp_m = (wid & 3) * 32, warp_n = (wid >> 2) * 64;
    const int q = lane >> 3;

    const uint32_t aBase = sb + A_OFF
        + (uint32_t)(warp_m + (lane & 7) + ((q & 1) << 3)) * RS + ((q >> 1) << 4);
    const uint32_t bBase = sb + B_OFF
        + (uint32_t)(warp_n + (lane & 7) + ((q >> 1) << 3)) * RS + ((q & 1) << 4);

    const unsigned short* Asrc = g_Ah + ((size_t)nb * WH + m0) * CC;
    const unsigned short* Bsrc = g_Bh + ((size_t)nb * CC + n0) * CC;

    float acc[2][8][4];
#pragma unroll
    for (int i = 0; i < 2; i++)
#pragma unroll
        for (int j = 0; j < 8; j++)
#pragma unroll
            for (int t = 0; t < 4; t++) acc[i][j][t] = 0.f;

    auto issue = [&](int c, int buf) {
        uint32_t d = sb + (uint32_t)buf * BUFB;
#pragma unroll
        for (int j = 0; j < 4; j++) {
            int o = tid + 256 * j, row = o >> 3, seg = o & 7;
            cp16(d + A_OFF + row * RS + seg * 16,
                 Asrc + (size_t)row * CC + c * 64 + seg * 8);
        }
#pragma unroll
        for (int j = 0; j < 4; j++) {
            int o = tid + 256 * j, row = o >> 3, seg = o & 7;
            cp16(d + B_OFF + row * RS + seg * 16,
                 Bsrc + (size_t)row * CC + c * 64 + seg * 8);
        }
        asm volatile("cp.async.commit_group;" ::: "memory");
    };

    issue(0, 0);
    issue(1, 1);
#pragma unroll
    for (int c = 0; c < 4; c++) {
        if (c < 3)
            asm volatile("cp.async.wait_group 1;" ::: "memory");
        else
            asm volatile("cp.async.wait_group 0;" ::: "memory");
        __syncthreads();
        if (c + 2 < 4) issue(c + 2, (c + 2) % 3);

        const uint32_t bo = (uint32_t)(c % 3) * BUFB;
#pragma unroll
        for (int ks = 0; ks < 4; ks++) {
            const uint32_t ko = bo + ks * 32;
            uint32_t ah[2][4];
            ldm4(ah[0], aBase + ko);
            ldm4(ah[1], aBase + ko + 16 * RS);
#pragma unroll
            for (int p = 0; p < 4; p++) {
                uint32_t bh[4];
                ldm4(bh, bBase + ko + p * 16 * RS);
                mma_f16(acc[0][2 * p],     ah[0], bh[0], bh[1]);
                mma_f16(acc[0][2 * p + 1], ah[0], bh[2], bh[3]);
                mma_f16(acc[1][2 * p],     ah[1], bh[0], bh[1]);
                mma_f16(acc[1][2 * p + 1], ah[1], bh[2], bh[3]);
            }
        }
    }

    const int g = lane >> 2, tg = lane & 3;
#pragma unroll
    for (int mt = 0; mt < 2; mt++) {
        int r0 = m0 + warp_m + mt * 16 + g;
        float pa0 = g_pa[(size_t)nb * WH + r0] * INV_BSCALE;
        float pa1 = g_pa[(size_t)nb * WH + r0 + 8] * INV_BSCALE;
        float* o0 = out + ((size_t)nb * WH + r0) * CC + n0 + warp_n + tg * 2;
        float* o1 = o0 + 8 * CC;
#pragma unroll
        for (int nt = 0; nt < 8; nt++) {
            float v0 = acc[mt][nt][0], v1 = acc[mt][nt][1];
            float v2 = acc[mt][nt][2], v3 = acc[mt][nt][3];
            v0 = (v0 > 0.f ? v0 : 0.1f * v0) * pa0;
            v1 = (v1 > 0.f ? v1 : 0.1f * v1) * pa0;
            v2 = (v2 > 0.f ? v2 : 0.1f * v2) * pa1;
            v3 = (v3 > 0.f ? v3 : 0.1f * v3) * pa1;
            *reinterpret_cast<float2*>(o0 + nt * 8) = make_float2(v0, v1);
            *reinterpret_cast<float2*>(o1 + nt * 8) = make_float2(v2, v3);
        }
    }
}

// ---------------------------------------------------------------------------
extern "C" void kernel_launch(void* const* d_in, const int* in_sizes, int n_in,
                              void* d_out, int out_size) {
    const float* in    = (const float*)d_in[0];  // [32,64,64,256]
    const float* style = (const float*)d_in[1];  // [32,256]
    const float* wd    = (const float*)d_in[2];  // [256,256]
    const float* wc    = (const float*)d_in[3];  // [1,1,256,256] -> [ci][co]
    float* out = (float*)d_out;

    static bool attr_set = false;
    if (!attr_set) {
        cudaFuncSetAttribute(k_conv_mma,
                             cudaFuncAttributeMaxDynamicSharedMemorySize, SMEMB);
        attr_set = true;
    }

    k_prep<<<NN + 64, 256>>>(style, wd, wc);
    k_pa_colsum<<<dim3(16, NN), 256>>>(in);
    k_soft<<<2 * NN, 256>>>();
    k_conv_mma<<<dim3(32, 2, NN), 256, SMEMB>>>(out);
}

// round 16
// speedup vs baseline: 1.2052x; 1.0978x over previous
#include <cuda_runtime.h>
#include <cuda_fp16.h>
#include <cstdint>

#define NN   32
#define WH   4096
#define CC   256
#define SCALE 0.0625f      // 1/sqrt(256)
#define BSCALE 64.0f       // pre-scale on B to keep folded ca*W in fp16 normal range
#define INV_BSCALE 0.015625f
#define NCHUNK 32          // colsum chunks per batch

// Scratch (device globals — no allocations allowed)
__device__ float g_q[NN * CC];
__device__ float g_partS[NN * NCHUNK * CC];
__device__ float g_palog[NN * WH];
__device__ float g_ca[NN * CC];
__device__ float g_pa[NN * WH];
__device__ __align__(16) unsigned short g_Ah[(size_t)NN * WH * CC]; // fp16(inputs)
__device__ __align__(16) unsigned short g_Wh[CC * CC];              // fp16(W^T) [co][ci]
__device__ __align__(16) unsigned short g_Bh[NN * CC * CC];         // per-batch 64*ca*W

// ---------------------------------------------------------------------------
// Helpers (baseline PTX — plain sm_103 target)
// ---------------------------------------------------------------------------
__device__ __forceinline__ void ldm4(uint32_t* r, uint32_t addr) {
    asm volatile("ldmatrix.sync.aligned.m8n8.x4.shared.b16 {%0,%1,%2,%3}, [%4];"
                 : "=r"(r[0]), "=r"(r[1]), "=r"(r[2]), "=r"(r[3]) : "r"(addr));
}
__device__ __forceinline__ void mma_f16(float* c, const uint32_t* a,
                                        uint32_t b0, uint32_t b1) {
    asm volatile(
        "mma.sync.aligned.m16n8k16.row.col.f32.f16.f16.f32 "
        "{%0,%1,%2,%3}, {%4,%5,%6,%7}, {%8,%9}, {%0,%1,%2,%3};"
        : "+f"(c[0]), "+f"(c[1]), "+f"(c[2]), "+f"(c[3])
        : "r"(a[0]), "r"(a[1]), "r"(a[2]), "r"(a[3]), "r"(b0), "r"(b1));
}
__device__ __forceinline__ uint32_t pack_h2(float a, float b) {
    __half2 t = __floats2half2_rn(a, b);
    return *reinterpret_cast<uint32_t*>(&t);
}
__device__ __forceinline__ void cp16(uint32_t dst, const void* src) {
    asm volatile("cp.async.cg.shared.global [%0], [%1], 16;"
                 :: "r"(dst), "l"(src) : "memory");
}

// ---------------------------------------------------------------------------
// K_prep (fused): blocks 0..31 -> q = leaky0.3(style@wd);
// blocks 32..95 -> tiled transpose wc[ci][co] fp32 -> g_Wh[co][ci] fp16.
// ---------------------------------------------------------------------------
__global__ void k_prep(const float* __restrict__ style,
                       const float* __restrict__ wd,
                       const float* __restrict__ wc) {
    int b = blockIdx.x;
    if (b < NN) {
        int n = b, c = threadIdx.x;
        __shared__ float s[CC];
        s[c] = style[n * CC + c];
        __syncthreads();
        float acc = 0.f;
#pragma unroll 8
        for (int k = 0; k < CC; k++) acc = fmaf(s[k], wd[k * CC + c], acc);
        g_q[n * CC + c] = acc > 0.f ? acc : 0.3f * acc;
    } else {
        __shared__ float tile[32][33];
        int bb = b - NN;
        int tx = threadIdx.x & 31, ty = threadIdx.x >> 5;
        int co0 = (bb & 7) * 32, ci0 = (bb >> 3) * 32;
#pragma unroll
        for (int j = 0; j < 4; j++)
            tile[ty + j * 8][tx] = wc[(size_t)(ci0 + ty + j * 8) * CC + co0 + tx];
        __syncthreads();
#pragma unroll
        for (int j = 0; j < 4; j++) {
            int co = co0 + ty + j * 8;
            g_Wh[(size_t)co * CC + ci0 + tx] =
                __half_as_ushort(__float2half_rn(tile[tx][ty + j * 8]));
        }
    }
}

// ---------------------------------------------------------------------------
// K2: one pass over inputs: pa_logits + partial column sums + fp16 copy of A.
// grid=(32 chunks, 32 n), block=256. 16 rows/warp, 2-row unrolled (MLP=4,
// two independent shuffle chains) — attacks the latency exposure seen at R15.
// ---------------------------------------------------------------------------
__global__ void k_pa_colsum(const float* __restrict__ in) {
    int n = blockIdx.y, chunk = blockIdx.x;
    int tid = threadIdx.x, lane = tid & 31, w = tid >> 5;

    const float4* q4 = reinterpret_cast<const float4*>(g_q + (size_t)n * CC);
    float4 qa = q4[lane * 2], qb = q4[lane * 2 + 1];

    float4 cs0 = {0.f, 0.f, 0.f, 0.f}, cs1 = {0.f, 0.f, 0.f, 0.f};
    int pbase = chunk * 128 + w * 16;
    const float4* base4 =
        reinterpret_cast<const float4*>(in + ((size_t)n * WH + pbase) * CC);

#pragma unroll 2
    for (int i = 0; i < 16; i += 2) {
        const float4* r0 = base4 + (size_t)i * (CC / 4);
        const float4* r1 = r0 + (CC / 4);
        float4 a0 = r0[lane * 2], a1 = r0[lane * 2 + 1];
        float4 b0 = r1[lane * 2], b1 = r1[lane * 2 + 1];

        float d0 = a0.x * qa.x + a0.y * qa.y + a0.z * qa.z + a0.w * qa.w
                 + a1.x * qb.x + a1.y * qb.y + a1.z * qb.z + a1.w * qb.w;
        float d1 = b0.x * qa.x + b0.y * qa.y + b0.z * qa.z + b0.w * qa.w
                 + b1.x * qb.x + b1.y * qb.y + b1.z * qb.z + b1.w * qb.w;

        cs0.x += a0.x + b0.x; cs0.y += a0.y + b0.y;
        cs0.z += a0.z + b0.z; cs0.w += a0.w + b0.w;
        cs1.x += a1.x + b1.x; cs1.y += a1.y + b1.y;
        cs1.z += a1.z + b1.z; cs1.w += a1.w + b1.w;

        uint4 h0, h1;
        h0.x = pack_h2(a0.x, a0.y); h0.y = pack_h2(a0.z, a0.w);
        h0.z = pack_h2(a1.x, a1.y); h0.w = pack_h2(a1.z, a1.w);
        h1.x = pack_h2(b0.x, b0.y); h1.y = pack_h2(b0.z, b0.w);
        h1.z = pack_h2(b1.x, b1.y); h1.w = pack_h2(b1.z, b1.w);
        unsigned short* adst = g_Ah + ((size_t)n * WH + pbase + i) * CC + lane * 8;
        *reinterpret_cast<uint4*>(adst) = h0;
        *reinterpret_cast<uint4*>(adst + CC) = h1;

#pragma unroll
        for (int o = 16; o; o >>= 1) {
            d0 += __shfl_xor_sync(0xffffffffu, d0, o);
            d1 += __shfl_xor_sync(0xffffffffu, d1, o);
        }
        if (lane == 0) {
            g_palog[(size_t)n * WH + pbase + i]     = d0 * SCALE;
            g_palog[(size_t)n * WH + pbase + i + 1] = d1 * SCALE;
        }
    }

    __shared__ float sm[8 * CC];
    float* smw = sm + w * CC + lane * 8;
    smw[0] = cs0.x; smw[1] = cs0.y; smw[2] = cs0.z; smw[3] = cs0.w;
    smw[4] = cs1.x; smw[5] = cs1.y; smw[6] = cs1.z; smw[7] = cs1.w;
    __syncthreads();
    float ssum = 0.f;
#pragma unroll
    for (int ww = 0; ww < 8; ww++) ssum += sm[ww * CC + tid];
    g_partS[((size_t)n * NCHUNK + chunk) * CC + tid] = ssum;
}

// ---------------------------------------------------------------------------
// K3 (fused): blocks 0..31 -> channel softmax; 32..63 -> position softmax
// ---------------------------------------------------------------------------
__global__ void k_soft() {
    int b = blockIdx.x, tid = threadIdx.x;
    __shared__ float red[256];
    if (b < NN) {
        int n = b;
        float S = 0.f;
#pragma unroll
        for (int k = 0; k < NCHUNK; k++)
            S += g_partS[((size_t)n * NCHUNK + k) * CC + tid];
        float logit = S * g_q[n * CC + tid] * SCALE;
        red[tid] = logit; __syncthreads();
        for (int s = 128; s; s >>= 1) {
            if (tid < s) red[tid] = fmaxf(red[tid], red[tid + s]);
            __syncthreads();
        }
        float m = red[0]; __syncthreads();
        float e = expf(logit - m);
        red[tid] = e; __syncthreads();
        for (int s = 128; s; s >>= 1) {
            if (tid < s) red[tid] += red[tid + s];
            __syncthreads();
        }
        g_ca[n * CC + tid] = e / red[0];
    } else {
        int n = b - NN;
        float v[16];
        float m = -1e30f;
#pragma unroll
        for (int i = 0; i < 16; i++) {
            v[i] = g_palog[(size_t)n * WH + i * 256 + tid];
            m = fmaxf(m, v[i]);
        }
        red[tid] = m; __syncthreads();
        for (int s = 128; s; s >>= 1) {
            if (tid < s) red[tid] = fmaxf(red[tid], red[tid + s]);
            __syncthreads();
        }
        m = red[0]; __syncthreads();
        float sum = 0.f;
#pragma unroll
        for (int i = 0; i < 16; i++) { v[i] = expf(v[i] - m); sum += v[i]; }
        red[tid] = sum; __syncthreads();
        for (int s = 128; s; s >>= 1) {
            if (tid < s) red[tid] += red[tid + s];
            __syncthreads();
        }
        float r = 1.f / red[0];
#pragma unroll
        for (int i = 0; i < 16; i++)
            g_pa[(size_t)n * WH + i * 256 + tid] = v[i] * r;
    }
}

// ---------------------------------------------------------------------------
// K_prepB: B_eff[n][co][ci] = fp16( 64 * ca[n][ci] * Wh[co][ci] ), coalesced.
// grid=(32 co-blocks of 8, 32 n), block=256. (Standalone — the R15 fusion
// into k_soft collapsed it onto 32 CTAs and regressed.)
// ---------------------------------------------------------------------------
__global__ void k_prepB() {
    int n = blockIdx.y;
    int co = blockIdx.x * 8 + (threadIdx.x >> 5);
    int ci0 = (threadIdx.x & 31) * 8;
    uint4 w = *reinterpret_cast<const uint4*>(g_Wh + (size_t)co * CC + ci0);
    const float4* cap = reinterpret_cast<const float4*>(g_ca + n * CC + ci0);
    float4 c0 = cap[0], c1 = cap[1];
    const __half2* wh = reinterpret_cast<const __half2*>(&w);
    uint4 o;
    float2 f;
    f = __half22float2(wh[0]);
    o.x = pack_h2(BSCALE * c0.x * f.x, BSCALE * c0.y * f.y);
    f = __half22float2(wh[1]);
    o.y = pack_h2(BSCALE * c0.z * f.x, BSCALE * c0.w * f.y);
    f = __half22float2(wh[2]);
    o.z = pack_h2(BSCALE * c1.x * f.x, BSCALE * c1.y * f.y);
    f = __half22float2(wh[3]);
    o.w = pack_h2(BSCALE * c1.z * f.x, BSCALE * c1.w * f.y);
    *reinterpret_cast<uint4*>(g_Bh + ((size_t)n * CC + co) * CC + ci0) = o;
}

// ---------------------------------------------------------------------------
// K4: HMMA fp16 GEMM, CTA tile 128x128, warp tile 32x64, 2 CTAs/SM,
// 3-buffer one-sync-per-chunk pipeline. Epilogue: leaky0.1 * pa/64.
// grid=(32 mtiles, 2 ntiles, 32 batch), block=256.
// ---------------------------------------------------------------------------
#define RS     144
#define A_OFF  0
#define B_OFF  18432
#define BUFB   36864
#define SMEMB  (3 * BUFB)            // 110592/CTA -> 221184/SM @2 CTAs

__global__ void __launch_bounds__(256, 2)
k_conv_mma(float* __restrict__ out) {
    extern __shared__ char smem[];
    const uint32_t sb = (uint32_t)__cvta_generic_to_shared(smem);
    const int tid = threadIdx.x, lane = tid & 31, wid = tid >> 5;
    const int nb = blockIdx.z;
    const int m0 = blockIdx.x * 128;
    const int n0 = blockIdx.y * 128;
    const int warp_m = (wid & 3) * 32, warp_n = (wid >> 2) * 64;
    const int q = lane >> 3;

    const uint32_t aBase = sb + A_OFF
        + (uint32_t)(warp_m + (lane & 7) + ((q & 1) << 3)) * RS + ((q >> 1) << 4);
    const uint32_t bBase = sb + B_OFF
        + (uint32_t)(warp_n + (lane & 7) + ((q >> 1) << 3)) * RS + ((q & 1) << 4);

    const unsigned short* Asrc = g_Ah + ((size_t)nb * WH + m0) * CC;
    const unsigned short* Bsrc = g_Bh + ((size_t)nb * CC + n0) * CC;

    float acc[2][8][4];
#pragma unroll
    for (int i = 0; i < 2; i++)
#pragma unroll
        for (int j = 0; j < 8; j++)
#pragma unroll
            for (int t = 0; t < 4; t++) acc[i][j][t] = 0.f;

    auto issue = [&](int c, int buf) {
        uint32_t d = sb + (uint32_t)buf * BUFB;
#pragma unroll
        for (int j = 0; j < 4; j++) {
            int o = tid + 256 * j, row = o >> 3, seg = o & 7;
            cp16(d + A_OFF + row * RS + seg * 16,
                 Asrc + (size_t)row * CC + c * 64 + seg * 8);
        }
#pragma unroll
        for (int j = 0; j < 4; j++) {
            int o = tid + 256 * j, row = o >> 3, seg = o & 7;
            cp16(d + B_OFF + row * RS + seg * 16,
                 Bsrc + (size_t)row * CC + c * 64 + seg * 8);
        }
        asm volatile("cp.async.commit_group;" ::: "memory");
    };

    issue(0, 0);
    issue(1, 1);
#pragma unroll
    for (int c = 0; c < 4; c++) {
        if (c < 3)
            asm volatile("cp.async.wait_group 1;" ::: "memory");
        else
            asm volatile("cp.async.wait_group 0;" ::: "memory");
        __syncthreads();
        if (c + 2 < 4) issue(c + 2, (c + 2) % 3);

        const uint32_t bo = (uint32_t)(c % 3) * BUFB;
#pragma unroll
        for (int ks = 0; ks < 4; ks++) {
            const uint32_t ko = bo + ks * 32;
            uint32_t ah[2][4];
            ldm4(ah[0], aBase + ko);
            ldm4(ah[1], aBase + ko + 16 * RS);
#pragma unroll
            for (int p = 0; p < 4; p++) {
                uint32_t bh[4];
                ldm4(bh, bBase + ko + p * 16 * RS);
                mma_f16(acc[0][2 * p],     ah[0], bh[0], bh[1]);
                mma_f16(acc[0][2 * p + 1], ah[0], bh[2], bh[3]);
                mma_f16(acc[1][2 * p],     ah[1], bh[0], bh[1]);
                mma_f16(acc[1][2 * p + 1], ah[1], bh[2], bh[3]);
            }
        }
    }

    const int g = lane >> 2, tg = lane & 3;
#pragma unroll
    for (int mt = 0; mt < 2; mt++) {
        int r0 = m0 + warp_m + mt * 16 + g;
        float pa0 = g_pa[(size_t)nb * WH + r0] * INV_BSCALE;
        float pa1 = g_pa[(size_t)nb * WH + r0 + 8] * INV_BSCALE;
        float* o0 = out + ((size_t)nb * WH + r0) * CC + n0 + warp_n + tg * 2;
        float* o1 = o0 + 8 * CC;
#pragma unroll
        for (int nt = 0; nt < 8; nt++) {
            float v0 = acc[mt][nt][0], v1 = acc[mt][nt][1];
            float v2 = acc[mt][nt][2], v3 = acc[mt][nt][3];
            v0 = (v0 > 0.f ? v0 : 0.1f * v0) * pa0;
            v1 = (v1 > 0.f ? v1 : 0.1f * v1) * pa0;
            v2 = (v2 > 0.f ? v2 : 0.1f * v2) * pa1;
            v3 = (v3 > 0.f ? v3 : 0.1f * v3) * pa1;
            *reinterpret_cast<float2*>(o0 + nt * 8) = make_float2(v0, v1);
            *reinterpret_cast<float2*>(o1 + nt * 8) = make_float2(v2, v3);
        }
    }
}

// ---------------------------------------------------------------------------
extern "C" void kernel_launch(void* const* d_in, const int* in_sizes, int n_in,
                              void* d_out, int out_size) {
    const float* in    = (const float*)d_in[0];  // [32,64,64,256]
    const float* style = (const float*)d_in[1];  // [32,256]
    const float* wd    = (const float*)d_in[2];  // [256,256]
    const float* wc    = (const float*)d_in[3];  // [1,1,256,256] -> [ci][co]
    float* out = (float*)d_out;

    static bool attr_set = false;
    if (!attr_set) {
        cudaFuncSetAttribute(k_conv_mma,
                             cudaFuncAttributeMaxDynamicSharedMemorySize, SMEMB);
        attr_set = true;
    }

    k_prep<<<NN + 64, 256>>>(style, wd, wc);
    k_pa_colsum<<<dim3(NCHUNK, NN), 256>>>(in);
    k_soft<<<2 * NN, 256>>>();
    k_prepB<<<dim3(32, NN), 256>>>();
    k_conv_mma<<<dim3(32, 2, NN), 256, SMEMB>>>(out);
}

// round 17
// speedup vs baseline: 1.2121x; 1.0057x over previous
#include <cuda_runtime.h>
#include <cuda_fp16.h>
#include <cstdint>

#define NN   32
#define WH   4096
#define CC   256
#define SCALE 0.0625f      // 1/sqrt(256)
#define BSCALE 64.0f       // pre-scale on B to keep folded ca*W in fp16 normal range
#define INV_BSCALE 0.015625f
#define NCHUNK 64          // colsum chunks per batch (64 rows each)

// Scratch (device globals — no allocations allowed)
__device__ float g_q[NN * CC];
__device__ float g_partS[NN * NCHUNK * CC];
__device__ float g_palog[NN * WH];
__device__ float g_ca[NN * CC];
__device__ float g_pa[NN * WH];
__device__ __align__(16) unsigned short g_Ah[(size_t)NN * WH * CC]; // fp16(inputs)
__device__ __align__(16) unsigned short g_Wh[CC * CC];              // fp16(W^T) [co][ci]
__device__ __align__(16) unsigned short g_Bh[NN * CC * CC];         // per-batch 64*ca*W

// ---------------------------------------------------------------------------
// Helpers (baseline PTX — plain sm_103 target)
// ---------------------------------------------------------------------------
__device__ __forceinline__ void ldm4(uint32_t* r, uint32_t addr) {
    asm volatile("ldmatrix.sync.aligned.m8n8.x4.shared.b16 {%0,%1,%2,%3}, [%4];"
                 : "=r"(r[0]), "=r"(r[1]), "=r"(r[2]), "=r"(r[3]) : "r"(addr));
}
__device__ __forceinline__ void mma_f16(float* c, const uint32_t* a,
                                        uint32_t b0, uint32_t b1) {
    asm volatile(
        "mma.sync.aligned.m16n8k16.row.col.f32.f16.f16.f32 "
        "{%0,%1,%2,%3}, {%4,%5,%6,%7}, {%8,%9}, {%0,%1,%2,%3};"
        : "+f"(c[0]), "+f"(c[1]), "+f"(c[2]), "+f"(c[3])
        : "r"(a[0]), "r"(a[1]), "r"(a[2]), "r"(a[3]), "r"(b0), "r"(b1));
}
__device__ __forceinline__ uint32_t pack_h2(float a, float b) {
    __half2 t = __floats2half2_rn(a, b);
    return *reinterpret_cast<uint32_t*>(&t);
}
__device__ __forceinline__ void cp16(uint32_t dst, const void* src) {
    asm volatile("cp.async.cg.shared.global [%0], [%1], 16;"
                 :: "r"(dst), "l"(src) : "memory");
}

// ---------------------------------------------------------------------------
// K_prep (fused): blocks 0..31 -> q = leaky0.3(style@wd);
// blocks 32..95 -> tiled transpose wc[ci][co] fp32 -> g_Wh[co][ci] fp16.
// ---------------------------------------------------------------------------
__global__ void k_prep(const float* __restrict__ style,
                       const float* __restrict__ wd,
                       const float* __restrict__ wc) {
    int b = blockIdx.x;
    if (b < NN) {
        int n = b, c = threadIdx.x;
        __shared__ float s[CC];
        s[c] = style[n * CC + c];
        __syncthreads();
        float acc = 0.f;
#pragma unroll 8
        for (int k = 0; k < CC; k++) acc = fmaf(s[k], wd[k * CC + c], acc);
        g_q[n * CC + c] = acc > 0.f ? acc : 0.3f * acc;
    } else {
        __shared__ float tile[32][33];
        int bb = b - NN;
        int tx = threadIdx.x & 31, ty = threadIdx.x >> 5;
        int co0 = (bb & 7) * 32, ci0 = (bb >> 3) * 32;
#pragma unroll
        for (int j = 0; j < 4; j++)
            tile[ty + j * 8][tx] = wc[(size_t)(ci0 + ty + j * 8) * CC + co0 + tx];
        __syncthreads();
#pragma unroll
        for (int j = 0; j < 4; j++) {
            int co = co0 + ty + j * 8;
            g_Wh[(size_t)co * CC + ci0 + tx] =
                __half_as_ushort(__float2half_rn(tile[tx][ty + j * 8]));
        }
    }
}

// ---------------------------------------------------------------------------
// K2: one pass over inputs: pa_logits + partial column sums + fp16 copy of A.
// grid=(64 chunks, 32 n), block=256. 8 rows/warp, 4-row unrolled (MLP=8,
// four independent shuffle chains).
// ---------------------------------------------------------------------------
__global__ void k_pa_colsum(const float* __restrict__ in) {
    int n = blockIdx.y, chunk = blockIdx.x;
    int tid = threadIdx.x, lane = tid & 31, w = tid >> 5;

    const float4* q4 = reinterpret_cast<const float4*>(g_q + (size_t)n * CC);
    float4 qa = q4[lane * 2], qb = q4[lane * 2 + 1];

    float4 cs0 = {0.f, 0.f, 0.f, 0.f}, cs1 = {0.f, 0.f, 0.f, 0.f};
    int pbase = chunk * 64 + w * 8;
    const float4* base4 =
        reinterpret_cast<const float4*>(in + ((size_t)n * WH + pbase) * CC);

#pragma unroll
    for (int i = 0; i < 8; i += 4) {
        const float4* r0 = base4 + (size_t)i * (CC / 4);
        const float4* r1 = r0 + (CC / 4);
        const float4* r2 = r1 + (CC / 4);
        const float4* r3 = r2 + (CC / 4);
        float4 a0 = r0[lane * 2], a1 = r0[lane * 2 + 1];
        float4 b0 = r1[lane * 2], b1 = r1[lane * 2 + 1];
        float4 c0 = r2[lane * 2], c1 = r2[lane * 2 + 1];
        float4 e0 = r3[lane * 2], e1 = r3[lane * 2 + 1];

        float d0 = a0.x * qa.x + a0.y * qa.y + a0.z * qa.z + a0.w * qa.w
                 + a1.x * qb.x + a1.y * qb.y + a1.z * qb.z + a1.w * qb.w;
        float d1 = b0.x * qa.x + b0.y * qa.y + b0.z * qa.z + b0.w * qa.w
                 + b1.x * qb.x + b1.y * qb.y + b1.z * qb.z + b1.w * qb.w;
        float d2 = c0.x * qa.x + c0.y * qa.y + c0.z * qa.z + c0.w * qa.w
                 + c1.x * qb.x + c1.y * qb.y + c1.z * qb.z + c1.w * qb.w;
        float d3 = e0.x * qa.x + e0.y * qa.y + e0.z * qa.z + e0.w * qa.w
                 + e1.x * qb.x + e1.y * qb.y + e1.z * qb.z + e1.w * qb.w;

        cs0.x += (a0.x + b0.x) + (c0.x + e0.x);
        cs0.y += (a0.y + b0.y) + (c0.y + e0.y);
        cs0.z += (a0.z + b0.z) + (c0.z + e0.z);
        cs0.w += (a0.w + b0.w) + (c0.w + e0.w);
        cs1.x += (a1.x + b1.x) + (c1.x + e1.x);
        cs1.y += (a1.y + b1.y) + (c1.y + e1.y);
        cs1.z += (a1.z + b1.z) + (c1.z + e1.z);
        cs1.w += (a1.w + b1.w) + (c1.w + e1.w);

        unsigned short* adst = g_Ah + ((size_t)n * WH + pbase + i) * CC + lane * 8;
        uint4 h;
        h.x = pack_h2(a0.x, a0.y); h.y = pack_h2(a0.z, a0.w);
        h.z = pack_h2(a1.x, a1.y); h.w = pack_h2(a1.z, a1.w);
        *reinterpret_cast<uint4*>(adst) = h;
        h.x = pack_h2(b0.x, b0.y); h.y = pack_h2(b0.z, b0.w);
        h.z = pack_h2(b1.x, b1.y); h.w = pack_h2(b1.z, b1.w);
        *reinterpret_cast<uint4*>(adst + CC) = h;
        h.x = pack_h2(c0.x, c0.y); h.y = pack_h2(c0.z, c0.w);
        h.z = pack_h2(c1.x, c1.y); h.w = pack_h2(c1.z, c1.w);
        *reinterpret_cast<uint4*>(adst + 2 * CC) = h;
        h.x = pack_h2(e0.x, e0.y); h.y = pack_h2(e0.z, e0.w);
        h.z = pack_h2(e1.x, e1.y); h.w = pack_h2(e1.z, e1.w);
        *reinterpret_cast<uint4*>(adst + 3 * CC) = h;

#pragma unroll
        for (int o = 16; o; o >>= 1) {
            d0 += __shfl_xor_sync(0xffffffffu, d0, o);
            d1 += __shfl_xor_sync(0xffffffffu, d1, o);
            d2 += __shfl_xor_sync(0xffffffffu, d2, o);
            d3 += __shfl_xor_sync(0xffffffffu, d3, o);
        }
        if (lane == 0) {
            float* pl = g_palog + (size_t)n * WH + pbase + i;
            pl[0] = d0 * SCALE;
            pl[1] = d1 * SCALE;
            pl[2] = d2 * SCALE;
            pl[3] = d3 * SCALE;
        }
    }

    __shared__ float sm[8 * CC];
    float* smw = sm + w * CC + lane * 8;
    smw[0] = cs0.x; smw[1] = cs0.y; smw[2] = cs0.z; smw[3] = cs0.w;
    smw[4] = cs1.x; smw[5] = cs1.y; smw[6] = cs1.z; smw[7] = cs1.w;
    __syncthreads();
    float ssum = 0.f;
#pragma unroll
    for (int ww = 0; ww < 8; ww++) ssum += sm[ww * CC + tid];
    g_partS[((size_t)n * NCHUNK + chunk) * CC + tid] = ssum;
}

// ---------------------------------------------------------------------------
// K3 (fused): blocks 0..31 -> channel softmax; 32..63 -> position softmax
// ---------------------------------------------------------------------------
__global__ void k_soft() {
    int b = blockIdx.x, tid = threadIdx.x;
    __shared__ float red[256];
    if (b < NN) {
        int n = b;
        float S = 0.f;
#pragma unroll
        for (int k = 0; k < NCHUNK; k++)
            S += g_partS[((size_t)n * NCHUNK + k) * CC + tid];
        float logit = S * g_q[n * CC + tid] * SCALE;
        red[tid] = logit; __syncthreads();
        for (int s = 128; s; s >>= 1) {
            if (tid < s) red[tid] = fmaxf(red[tid], red[tid + s]);
            __syncthreads();
        }
        float m = red[0]; __syncthreads();
        float e = expf(logit - m);
        red[tid] = e; __syncthreads();
        for (int s = 128; s; s >>= 1) {
            if (tid < s) red[tid] += red[tid + s];
            __syncthreads();
        }
        g_ca[n * CC + tid] = e / red[0];
    } else {
        int n = b - NN;
        float v[16];
        float m = -1e30f;
#pragma unroll
        for (int i = 0; i < 16; i++) {
            v[i] = g_palog[(size_t)n * WH + i * 256 + tid];
            m = fmaxf(m, v[i]);
        }
        red[tid] = m; __syncthreads();
        for (int s = 128; s; s >>= 1) {
            if (tid < s) red[tid] = fmaxf(red[tid], red[tid + s]);
            __syncthreads();
        }
        m = red[0]; __syncthreads();
        float sum = 0.f;
#pragma unroll
        for (int i = 0; i < 16; i++) { v[i] = expf(v[i] - m); sum += v[i]; }
        red[tid] = sum; __syncthreads();
        for (int s = 128; s; s >>= 1) {
            if (tid < s) red[tid] += red[tid + s];
            __syncthreads();
        }
        float r = 1.f / red[0];
#pragma unroll
        for (int i = 0; i < 16; i++)
            g_pa[(size_t)n * WH + i * 256 + tid] = v[i] * r;
    }
}

// ---------------------------------------------------------------------------
// K_prepB: B_eff[n][co][ci] = fp16( 64 * ca[n][ci] * Wh[co][ci] ), coalesced.
// grid=(32 co-blocks of 8, 32 n), block=256.
// ---------------------------------------------------------------------------
__global__ void k_prepB() {
    int n = blockIdx.y;
    int co = blockIdx.x * 8 + (threadIdx.x >> 5);
    int ci0 = (threadIdx.x & 31) * 8;
    uint4 w = *reinterpret_cast<const uint4*>(g_Wh + (size_t)co * CC + ci0);
    const float4* cap = reinterpret_cast<const float4*>(g_ca + n * CC + ci0);
    float4 c0 = cap[0], c1 = cap[1];
    const __half2* wh = reinterpret_cast<const __half2*>(&w);
    uint4 o;
    float2 f;
    f = __half22float2(wh[0]);
    o.x = pack_h2(BSCALE * c0.x * f.x, BSCALE * c0.y * f.y);
    f = __half22float2(wh[1]);
    o.y = pack_h2(BSCALE * c0.z * f.x, BSCALE * c0.w * f.y);
    f = __half22float2(wh[2]);
    o.z = pack_h2(BSCALE * c1.x * f.x, BSCALE * c1.y * f.y);
    f = __half22float2(wh[3]);
    o.w = pack_h2(BSCALE * c1.z * f.x, BSCALE * c1.w * f.y);
    *reinterpret_cast<uint4*>(g_Bh + ((size_t)n * CC + co) * CC + ci0) = o;
}

// ---------------------------------------------------------------------------
// K4: HMMA fp16 GEMM, CTA tile 128x128, warp tile 32x64, 2 CTAs/SM,
// 3-buffer one-sync-per-chunk pipeline. Epilogue: leaky0.1 * pa/64.
// grid=(32 mtiles, 2 ntiles, 32 batch), block=256.
// ---------------------------------------------------------------------------
#define RS     144
#define A_OFF  0
#define B_OFF  18432
#define BUFB   36864
#define SMEMB  (3 * BUFB)            // 110592/CTA -> 221184/SM @2 CTAs

__global__ void __launch_bounds__(256, 2)
k_conv_mma(float* __restrict__ out) {
    extern __shared__ char smem[];
    const uint32_t sb = (uint32_t)__cvta_generic_to_shared(smem);
    const int tid = threadIdx.x, lane = tid & 31, wid = tid >> 5;
    const int nb = blockIdx.z;
    const int m0 = blockIdx.x * 128;
    const int n0 = blockIdx.y * 128;
    const int warp_m = (wid & 3) * 32, warp_n = (wid >> 2) * 64;
    const int q = lane >> 3;

    const uint32_t aBase = sb + A_OFF
        + (uint32_t)(warp_m + (lane & 7) + ((q & 1) << 3)) * RS + ((q >> 1) << 4);
    const uint32_t bBase = sb + B_OFF
        + (uint32_t)(warp_n + (lane & 7) + ((q >> 1) << 3)) * RS + ((q & 1) << 4);

    const unsigned short* Asrc = g_Ah + ((size_t)nb * WH + m0) * CC;
    const unsigned short* Bsrc = g_Bh + ((size_t)nb * CC + n0) * CC;

    float acc[2][8][4];
#pragma unroll
    for (int i = 0; i < 2; i++)
#pragma unroll
        for (int j = 0; j < 8; j++)
#pragma unroll
            for (int t = 0; t < 4; t++) acc[i][j][t] = 0.f;

    auto issue = [&](int c, int buf) {
        uint32_t d = sb + (uint32_t)buf * BUFB;
#pragma unroll
        for (int j = 0; j < 4; j++) {
            int o = tid + 256 * j, row = o >> 3, seg = o & 7;
            cp16(d + A_OFF + row * RS + seg * 16,
                 Asrc + (size_t)row * CC + c * 64 + seg * 8);
        }
#pragma unroll
        for (int j = 0; j < 4; j++) {
            int o = tid + 256 * j, row = o >> 3, seg = o & 7;
            cp16(d + B_OFF + row * RS + seg * 16,
                 Bsrc + (size_t)row * CC + c * 64 + seg * 8);
        }
        asm volatile("cp.async.commit_group;" ::: "memory");
    };

    issue(0, 0);
    issue(1, 1);
#pragma unroll
    for (int c = 0; c < 4; c++) {
        if (c < 3)
            asm volatile("cp.async.wait_group 1;" ::: "memory");
        else
            asm volatile("cp.async.wait_group 0;" ::: "memory");
        __syncthreads();
        if (c + 2 < 4) issue(c + 2, (c + 2) % 3);

        const uint32_t bo = (uint32_t)(c % 3) * BUFB;
#pragma unroll
        for (int ks = 0; ks < 4; ks++) {
            const uint32_t ko = bo + ks * 32;
            uint32_t ah[2][4];
            ldm4(ah[0], aBase + ko);
            ldm4(ah[1], aBase + ko + 16 * RS);
#pragma unroll
            for (int p = 0; p < 4; p++) {
                uint32_t bh[4];
                ldm4(bh, bBase + ko + p * 16 * RS);
                mma_f16(acc[0][2 * p],     ah[0], bh[0], bh[1]);
                mma_f16(acc[0][2 * p + 1], ah[0], bh[2], bh[3]);
                mma_f16(acc[1][2 * p],     ah[1], bh[0], bh[1]);
                mma_f16(acc[1][2 * p + 1], ah[1], bh[2], bh[3]);
            }
        }
    }

    const int g = lane >> 2, tg = lane & 3;
#pragma unroll
    for (int mt = 0; mt < 2; mt++) {
        int r0 = m0 + warp_m + mt * 16 + g;
        float pa0 = g_pa[(size_t)nb * WH + r0] * INV_BSCALE;
        float pa1 = g_pa[(size_t)nb * WH + r0 + 8] * INV_BSCALE;
        float* o0 = out + ((size_t)nb * WH + r0) * CC + n0 + warp_n + tg * 2;
        float* o1 = o0 + 8 * CC;
#pragma unroll
        for (int nt = 0; nt < 8; nt++) {
            float v0 = acc[mt][nt][0], v1 = acc[mt][nt][1];
            float v2 = acc[mt][nt][2], v3 = acc[mt][nt][3];
            v0 = (v0 > 0.f ? v0 : 0.1f * v0) * pa0;
            v1 = (v1 > 0.f ? v1 : 0.1f * v1) * pa0;
            v2 = (v2 > 0.f ? v2 : 0.1f * v2) * pa1;
            v3 = (v3 > 0.f ? v3 : 0.1f * v3) * pa1;
            *reinterpret_cast<float2*>(o0 + nt * 8) = make_float2(v0, v1);
            *reinterpret_cast<float2*>(o1 + nt * 8) = make_float2(v2, v3);
        }
    }
}

// ---------------------------------------------------------------------------
extern "C" void kernel_launch(void* const* d_in, const int* in_sizes, int n_in,
                              void* d_out, int out_size) {
    const float* in    = (const float*)d_in[0];  // [32,64,64,256]
    const float* style = (const float*)d_in[1];  // [32,256]
    const float* wd    = (const float*)d_in[2];  // [256,256]
    const float* wc    = (const float*)d_in[3];  // [1,1,256,256] -> [ci][co]
    float* out = (float*)d_out;

    static bool attr_set = false;
    if (!attr_set) {
        cudaFuncSetAttribute(k_conv_mma,
                             cudaFuncAttributeMaxDynamicSharedMemorySize, SMEMB);
        attr_set = true;
    }

    k_prep<<<NN + 64, 256>>>(style, wd, wc);
    k_pa_colsum<<<dim3(NCHUNK, NN), 256>>>(in);
    k_soft<<<2 * NN, 256>>>();
    k_prepB<<<dim3(32, NN), 256>>>();
    k_conv_mma<<<dim3(32, 2, NN), 256, SMEMB>>>(out);
}